// round 9
// baseline (speedup 1.0000x reference)
#include <cuda_runtime.h>
#include <cuda_bf16.h>
#include <cstdint>
#include <cmath>

#define BATCH 16384
#define NV 1024
#define NH 1024
#define HD 64
#define KSTEPS 10

__device__ float         g_bmod[(size_t)BATCH * NV];
__device__ float         g_cmod[(size_t)BATCH * NH];
__device__ float         g_a   [(size_t)BATCH * NV];
__device__ float         g_vwd [(size_t)BATCH * NV];   // recovered v_data@W for FE-data
__device__ __nv_bfloat16 g_vb  [(size_t)BATCH * NV];
__device__ __nv_bfloat16 g_hb  [(size_t)BATCH * NH];
__device__ float         g_u   [BATCH];
__device__ __nv_bfloat16 g_Whi[NV*NH], g_Wlo[NV*NH];   // [v][h] (k=h contiguous)
__device__ __nv_bfloat16 g_Thi[NV*NH], g_Tlo[NV*NH];   // [h][v] (k=v contiguous)
__device__ float         g_colsum[NH];
__device__ double        g_acc;

__host__ __device__ __forceinline__ void tf2x32(uint32_t k0, uint32_t k1,
                                                uint32_t x0, uint32_t x1,
                                                uint32_t& o0, uint32_t& o1) {
  uint32_t ks2 = k0 ^ k1 ^ 0x1BD11BDAu;
#define TF_R(r) { x0 += x1; x1 = (x1 << (r)) | (x1 >> (32 - (r))); x1 ^= x0; }
  x0 += k0; x1 += k1;
  TF_R(13) TF_R(15) TF_R(26) TF_R(6)   x0 += k1;  x1 += ks2 + 1u;
  TF_R(17) TF_R(29) TF_R(16) TF_R(24)  x0 += ks2; x1 += k0 + 2u;
  TF_R(13) TF_R(15) TF_R(26) TF_R(6)   x0 += k0;  x1 += k1 + 3u;
  TF_R(17) TF_R(29) TF_R(16) TF_R(24)  x0 += k1;  x1 += ks2 + 4u;
  TF_R(13) TF_R(15) TF_R(26) TF_R(6)   x0 += ks2; x1 += k0 + 5u;
#undef TF_R
  o0 = x0; o1 = x1;
}
__device__ __forceinline__ float jax_uniform(uint32_t ka, uint32_t kb, uint32_t idx) {
  uint32_t o0, o1; tf2x32(ka, kb, 0u, idx, o0, o1);
  return __uint_as_float(((o0 ^ o1) >> 9) | 0x3f800000u) - 1.0f;
}
__device__ __forceinline__ float sigmoidf_(float x)  { return 1.0f / (1.0f + expf(-x)); }
__device__ __forceinline__ float softplusf_(float x) { return fmaxf(x, 0.0f) + log1pf(expf(-fabsf(x))); }

__device__ __forceinline__ uint32_t smem_to_u32(const void* p) {
  uint32_t a;
  asm("{ .reg .u64 t; cvta.to.shared.u64 t, %1; cvt.u32.u64 %0, t; }" : "=r"(a) : "l"(p));
  return a;
}
__device__ __forceinline__ void sts128(uint32_t a, uint4 v) {
  asm volatile("st.shared.v4.b32 [%0], {%1,%2,%3,%4};" :: "r"(a), "r"(v.x), "r"(v.y), "r"(v.z), "r"(v.w) : "memory");
}
#define LDSM_X4(r0, r1, r2, r3, addr) \
  asm volatile("ldmatrix.sync.aligned.m8n8.x4.shared.b16 {%0,%1,%2,%3}, [%4];" \
    : "=r"(r0), "=r"(r1), "=r"(r2), "=r"(r3) : "r"(addr))

// ---------------- bf16 mma GEMM ----------------
// Tile 64(M) x 128(N), 16 k-blocks of 64, W = Whi + Wlo (2-way bf16 split)
// grid (8, 256) = 2048 CTAs -> 6.92 waves at occ 2 (kills wave quantization)
// MODE 1: A=v_branch(g_vb,u), B=T* -> sample h into g_hb (S0: also recover vdata@W -> g_vwd)
// MODE 2: A=g_hb, B=W* -> g_a ;  MODE 4: A=g_vb, B=T* -> g_a
#define NKB 16
#define ASTR 144
#define TILE_A (64 * ASTR)             // 9216
#define TILE_B (128 * ASTR)            // 18432
#define SM_TOTAL (2 * TILE_A + 4 * TILE_B)  // 92160

template<int MODE, bool S0>
__global__ void __launch_bounds__(256, 2) gemm_mma(uint32_t ka, uint32_t kb) {
  extern __shared__ char smem[];
  uint32_t sbase = smem_to_u32(smem);
  int tid = threadIdx.x, lane = tid & 31, wid = tid >> 5;
  int wm = wid & 1, wn = wid >> 1;             // warp grid 2(M) x 4(N), warp tile 32x32
  int gq = lane >> 2, tg = lane & 3;
  int bm = blockIdx.y * 64, bn = blockIdx.x * 128;

  const __nv_bfloat16* A  = (MODE == 2) ? g_hb : g_vb;
  const __nv_bfloat16* Bh = (MODE == 2) ? g_Whi : g_Thi;
  const __nv_bfloat16* Bl = (MODE == 2) ? g_Wlo : g_Tlo;

  int arow[2]; uint32_t uxr[2];
  arow[0] = tid >> 3; arow[1] = arow[0] + 32;
  uxr[0] = uxr[1] = 0u;
  if (MODE == 1) {
    uxr[0] = (g_u[bm + arow[0]] == 0.0f) ? 0x3F803F80u : 0u;
    uxr[1] = (g_u[bm + arow[1]] == 0.0f) ? 0x3F803F80u : 0u;
  }
  int brow[4];
#pragma unroll
  for (int q = 0; q < 4; q++) brow[q] = (tid >> 3) + 32 * q;
  int seg = tid & 7;

  uint4 aregs[2];
  auto ldgA = [&](int kbk) {
    int kin = kbk * 64;
#pragma unroll
    for (int q = 0; q < 2; q++) {
      uint4 v = *(const uint4*)(A + (((size_t)(bm + arow[q])) << 10) + kin + seg * 8);
      if (MODE == 1) { v.x ^= uxr[q]; v.y ^= uxr[q]; v.z ^= uxr[q]; v.w ^= uxr[q]; }
      aregs[q] = v;
    }
  };
  auto stsA = [&](int buf) {
    uint32_t base = sbase + buf * TILE_A;
#pragma unroll
    for (int q = 0; q < 2; q++)
      sts128(base + arow[q] * ASTR + seg * 16, aregs[q]);
  };
  auto issueB = [&](int kbk) {
    int kin = kbk * 64, buf = kbk & 1;
    uint32_t bh = sbase + 2 * TILE_A + buf * TILE_B;
    uint32_t bl = sbase + 2 * TILE_A + 2 * TILE_B + buf * TILE_B;
#pragma unroll
    for (int q = 0; q < 4; q++) {
      uint32_t soff = brow[q] * ASTR + seg * 16;
      size_t goff = (((size_t)(bn + brow[q])) << 10) + kin + seg * 8;
      asm volatile("cp.async.cg.shared.global [%0], [%1], 16;" :: "r"(bh + soff), "l"((const void*)(Bh + goff)) : "memory");
      asm volatile("cp.async.cg.shared.global [%0], [%1], 16;" :: "r"(bl + soff), "l"((const void*)(Bl + goff)) : "memory");
    }
    asm volatile("cp.async.commit_group;" ::: "memory");
  };

  float acc[2][4][4];
#pragma unroll
  for (int i = 0; i < 2; i++)
#pragma unroll
    for (int j = 0; j < 4; j++)
#pragma unroll
      for (int q = 0; q < 4; q++) acc[i][j][q] = 0.f;

  // prologue
  ldgA(0); stsA(0);
  issueB(0);
  ldgA(1);

  uint32_t a_l15 = (uint32_t)(lane & 15), a_hi16 = (uint32_t)((lane >> 4) << 4);
  uint32_t b_row = (uint32_t)((lane & 7) + ((lane >> 4) << 3));
  uint32_t b_k16 = (uint32_t)(((lane >> 3) & 1) << 4);

  for (int kbk = 0; kbk < NKB; kbk++) {
    asm volatile("cp.async.wait_group 0;" ::: "memory");
    __syncthreads();                      // single sync per k-block
    if (kbk + 1 < NKB) { issueB(kbk + 1); stsA((kbk + 1) & 1); }
    if (kbk + 2 < NKB) ldgA(kbk + 2);

    uint32_t Ab  = sbase + (kbk & 1) * TILE_A;
    uint32_t Bhb = sbase + 2 * TILE_A + (kbk & 1) * TILE_B;
    uint32_t Blb = sbase + 2 * TILE_A + 2 * TILE_B + (kbk & 1) * TILE_B;
#pragma unroll
    for (int ks = 0; ks < 4; ks++) {
      uint32_t afr[2][4];
#pragma unroll
      for (int i = 0; i < 2; i++) {
        uint32_t addr = Ab + ((uint32_t)(wm * 32 + i * 16) + a_l15) * ASTR + (uint32_t)(ks * 32) + a_hi16;
        LDSM_X4(afr[i][0], afr[i][1], afr[i][2], afr[i][3], addr);
      }
      uint32_t bhf[4][2], blf[4][2];
#pragma unroll
      for (int jp = 0; jp < 2; jp++) {
        uint32_t rowoff = ((uint32_t)(wn * 32 + jp * 16) + b_row) * ASTR + (uint32_t)(ks * 32) + b_k16;
        LDSM_X4(bhf[2*jp][0], bhf[2*jp][1], bhf[2*jp+1][0], bhf[2*jp+1][1], Bhb + rowoff);
        LDSM_X4(blf[2*jp][0], blf[2*jp][1], blf[2*jp+1][0], blf[2*jp+1][1], Blb + rowoff);
      }
#pragma unroll
      for (int i = 0; i < 2; i++)
#pragma unroll
        for (int j = 0; j < 4; j++)
          asm volatile("mma.sync.aligned.m16n8k16.row.col.f32.bf16.bf16.f32 "
            "{%0,%1,%2,%3}, {%4,%5,%6,%7}, {%8,%9}, {%0,%1,%2,%3};"
            : "+f"(acc[i][j][0]), "+f"(acc[i][j][1]), "+f"(acc[i][j][2]), "+f"(acc[i][j][3])
            : "r"(afr[i][0]), "r"(afr[i][1]), "r"(afr[i][2]), "r"(afr[i][3]),
              "r"(bhf[j][0]), "r"(bhf[j][1]));
#pragma unroll
      for (int i = 0; i < 2; i++)
#pragma unroll
        for (int j = 0; j < 4; j++)
          asm volatile("mma.sync.aligned.m16n8k16.row.col.f32.bf16.bf16.f32 "
            "{%0,%1,%2,%3}, {%4,%5,%6,%7}, {%8,%9}, {%0,%1,%2,%3};"
            : "+f"(acc[i][j][0]), "+f"(acc[i][j][1]), "+f"(acc[i][j][2]), "+f"(acc[i][j][3])
            : "r"(afr[i][0]), "r"(afr[i][1]), "r"(afr[i][2]), "r"(afr[i][3]),
              "r"(blf[j][0]), "r"(blf[j][1]));
    }
  }

  // epilogue
#pragma unroll
  for (int i = 0; i < 2; i++) {
    int row0 = bm + wm * 32 + i * 16 + gq;
#pragma unroll
    for (int j = 0; j < 4; j++) {
      int col = bn + wn * 32 + j * 8 + tg * 2;
#pragma unroll
      for (int half = 0; half < 2; half++) {
        int r = row0 + half * 8;
        uint32_t idx = ((uint32_t)r << 10) | (uint32_t)col;
        float v0 = acc[i][j][half * 2], v1 = acc[i][j][half * 2 + 1];
        if (MODE == 1) {
          if (S0) {   // recover vdata@W: u=1 -> D ; u=0 -> colsum - D
            float uu = g_u[r];
            float w0 = (uu != 0.0f) ? v0 : g_colsum[col]     - v0;
            float w1 = (uu != 0.0f) ? v1 : g_colsum[col + 1] - v1;
            *(float2*)(g_vwd + idx) = make_float2(w0, w1);
          }
          float2 cm = *(const float2*)(g_cmod + idx);
          float p0 = sigmoidf_(v0 + cm.x), p1 = sigmoidf_(v1 + cm.y);
          float u0 = jax_uniform(ka, kb, idx), u1 = jax_uniform(ka, kb, idx + 1);
          __nv_bfloat162 hv;
          hv.x = __float2bfloat16((u0 < p0) ? 1.0f : 0.0f);
          hv.y = __float2bfloat16((u1 < p1) ? 1.0f : 0.0f);
          *(__nv_bfloat162*)(g_hb + idx) = hv;
        } else {
          *(float2*)(g_a + idx) = make_float2(v0, v1);
        }
      }
    }
  }
}

// ---- hypernetwork biases ----
#define BT_ROWS 16
__global__ void biases_kernel(const float* __restrict__ cond, const float* __restrict__ b,
                              const float* __restrict__ c, const float* __restrict__ fc1w,
                              const float* __restrict__ fc1b, const float* __restrict__ fc2w,
                              const float* __restrict__ fc2b) {
  __shared__ float xs[BT_ROWS][HD];
  int r0 = blockIdx.x * BT_ROWS, tid = threadIdx.x;
  for (int t = tid; t < BT_ROWS * HD; t += blockDim.x) {
    int r = t / HD, d = t % HD;
    xs[r][d] = tanhf(cond[r0 + r] * fc1w[d] + fc1b[d]);
  }
  __syncthreads();
  for (int j = tid; j < NV + NH; j += blockDim.x) {
    int gw, bw;
    if (j < NV) { gw = j; bw = NV + j; } else { gw = 2*NV + (j-NV); bw = 2*NV + NH + (j-NV); }
    const float* wg = fc2w + (size_t)gw * HD;
    const float* wb = fc2w + (size_t)bw * HD;
    float accG[BT_ROWS], accB[BT_ROWS];
#pragma unroll
    for (int r = 0; r < BT_ROWS; r++) { accG[r] = 0.f; accB[r] = 0.f; }
    for (int d = 0; d < HD; d++) {
      float g = wg[d], bb = wb[d];
#pragma unroll
      for (int r = 0; r < BT_ROWS; r++) { float x = xs[r][d]; accG[r] += g*x; accB[r] += bb*x; }
    }
    float gb = fc2b[gw], bbia = fc2b[bw];
    if (j < NV) {
      float bj = b[j];
      for (int r = 0; r < BT_ROWS; r++)
        g_bmod[(size_t)(r0 + r)*NV + j] = (1.0f + accG[r] + gb)*bj + (accB[r] + bbia);
    } else {
      int hh = j - NV; float ch = c[hh];
      for (int r = 0; r < BT_ROWS; r++)
        g_cmod[(size_t)(r0 + r)*NH + hh] = (1.0f + accG[r] + gb)*ch + (accB[r] + bbia);
    }
  }
}

// ---- W 2-way split, both layouts ----
__device__ __forceinline__ void split2(float w, __nv_bfloat16& hi, __nv_bfloat16& lo) {
  hi = __float2bfloat16(w);
  lo = __float2bfloat16(w - __bfloat162float(hi));
}
__global__ void splitT_kernel(const float* __restrict__ W) {
  __shared__ float t[32][33];
  int bx = blockIdx.x*32, by = blockIdx.y*32;
  int tx = threadIdx.x, ty = threadIdx.y;
  for (int i = 0; i < 32; i += 8) {
    int r = by + ty + i, cc = bx + tx;
    float w = W[(size_t)r*NH + cc];
    t[ty + i][tx] = w;
    __nv_bfloat16 hi, lo; split2(w, hi, lo);
    size_t ix = (size_t)r*NH + cc;
    g_Whi[ix] = hi; g_Wlo[ix] = lo;
  }
  __syncthreads();
  for (int i = 0; i < 32; i += 8) {
    float w = t[tx][ty + i];
    __nv_bfloat16 hi, lo; split2(w, hi, lo);
    size_t ix = (size_t)(bx + ty + i)*NV + by + tx;
    g_Thi[ix] = hi; g_Tlo[ix] = lo;
  }
}

__global__ void colsum_kernel(const float* __restrict__ W) {
  int h = blockIdx.x * blockDim.x + threadIdx.x;
  float s = 0.f;
  for (int v2 = 0; v2 < NV; v2++) s += W[(size_t)v2*NH + h];
  g_colsum[h] = s;
}
__global__ void copyv_kernel(const float* __restrict__ v_data) {
  int i = blockIdx.x * blockDim.x + threadIdx.x;
  float4 v = ((const float4*)v_data)[i];
  ushort4 o;
  o.x = __bfloat16_as_ushort(__float2bfloat16(v.x));
  o.y = __bfloat16_as_ushort(__float2bfloat16(v.y));
  o.z = __bfloat16_as_ushort(__float2bfloat16(v.z));
  o.w = __bfloat16_as_ushort(__float2bfloat16(v.w));
  ((ushort4*)g_vb)[i] = o;
}
__global__ void u0_kernel(uint32_t ka, uint32_t kb) {
  int i = blockIdx.x * blockDim.x + threadIdx.x;
  if (i == 0) g_acc = 0.0;
  if (i < BATCH) g_u[i] = (jax_uniform(ka, kb, (uint32_t)i) < 0.5f) ? 1.0f : 0.0f;
}

// ---- fused dE + sample u + sample v ----
__global__ void dEsampleV_kernel(uint32_t kua, uint32_t kub, uint32_t kva, uint32_t kvb) {
  int row = blockIdx.x, tid = threadIdx.x, wrp = tid >> 5, lane = tid & 31;
  const float4 a4 = ((const float4*)(g_a    + (size_t)row*NV))[tid];
  const float4 b4 = ((const float4*)(g_bmod + (size_t)row*NV))[tid];
  ushort4 vu = ((const ushort4*)(g_vb + (size_t)row*NV))[tid];
  float v0 = __bfloat162float(__ushort_as_bfloat16(vu.x));
  float v1 = __bfloat162float(__ushort_as_bfloat16(vu.y));
  float v2 = __bfloat162float(__ushort_as_bfloat16(vu.z));
  float v3 = __bfloat162float(__ushort_as_bfloat16(vu.w));
  float sa = a4.x+a4.y+a4.z+a4.w, sb = b4.x+b4.y+b4.z+b4.w;
  float sva = v0*a4.x+v1*a4.y+v2*a4.z+v3*a4.w, svb = v0*b4.x+v1*b4.y+v2*b4.z+v3*b4.w;
#pragma unroll
  for (int o = 16; o > 0; o >>= 1) {
    sa  += __shfl_down_sync(0xffffffffu, sa,  o);
    sb  += __shfl_down_sync(0xffffffffu, sb,  o);
    sva += __shfl_down_sync(0xffffffffu, sva, o);
    svb += __shfl_down_sync(0xffffffffu, svb, o);
  }
  __shared__ float red[4][8];
  __shared__ float uval;
  if (lane == 0) { red[0][wrp] = sa; red[1][wrp] = sb; red[2][wrp] = sva; red[3][wrp] = svb; }
  __syncthreads();
  if (tid == 0) {
    float SA=0, SB=0, SVA=0, SVB=0;
#pragma unroll
    for (int w = 0; w < 8; w++) { SA += red[0][w]; SB += red[1][w]; SVA += red[2][w]; SVB += red[3][w]; }
    float dE = -SB - SA + 2.0f*SVB + 2.0f*SVA;
    float un = jax_uniform(kua, kub, (uint32_t)row);
    float u  = (un < sigmoidf_(dE)) ? 1.0f : 0.0f;
    g_u[row] = u; uval = u;
  }
  __syncthreads();
  float u = uval;
  float aa[4] = {a4.x, a4.y, a4.z, a4.w}, bb[4] = {b4.x, b4.y, b4.z, b4.w};
  ushort4 outv; unsigned short* op = (unsigned short*)&outv;
#pragma unroll
  for (int q = 0; q < 4; q++) {
    uint32_t idx = (uint32_t)row*1024u + (uint32_t)(tid*4 + q);
    float p  = sigmoidf_(aa[q] + bb[q]);
    float un = jax_uniform(kva, kvb, idx);
    float vb = (un < p) ? 1.0f : 0.0f;
    op[q] = __bfloat16_as_ushort(__float2bfloat16((u != 0.0f) ? vb : 1.0f - vb));
  }
  ((ushort4*)(g_vb + (size_t)row*NV))[tid] = outv;
}

// ---- free energy ----
// USE_GV: v from g_vb (model) else vparam (data). WSRC 0: vW from g_vwd ; 1: from g_a
template<bool USE_GV, int WSRC>
__global__ void fe_kernel(const float* __restrict__ vparam, double sign) {
  int row = blockIdx.x, tid = threadIdx.x, wrp = tid >> 5, lane = tid & 31;
  const float* br = g_bmod + (size_t)row*NV;
  const float* wr = (WSRC == 0 ? g_vwd : g_a) + (size_t)row*NH;
  const float* cr = g_cmod + (size_t)row*NH;
  float spn = 0, spf = 0, svb = 0, sb = 0;
  for (int j = tid; j < NV; j += 256) {
    float vv = USE_GV ? __bfloat162float(g_vb[(size_t)row*NV + j]) : vparam[(size_t)row*NV + j];
    float bbv = br[j];
    svb += vv*bbv; sb += bbv;
    float w = wr[j], cm = cr[j];
    spn += softplusf_(w + cm);
    spf += softplusf_(g_colsum[j] - w + cm);
  }
#pragma unroll
  for (int o = 16; o > 0; o >>= 1) {
    spn += __shfl_down_sync(0xffffffffu, spn, o);
    spf += __shfl_down_sync(0xffffffffu, spf, o);
    svb += __shfl_down_sync(0xffffffffu, svb, o);
    sb  += __shfl_down_sync(0xffffffffu, sb,  o);
  }
  __shared__ float red[4][8];
  if (lane == 0) { red[0][wrp] = spn; red[1][wrp] = spf; red[2][wrp] = svb; red[3][wrp] = sb; }
  __syncthreads();
  if (tid == 0) {
    float SPN=0, SPF=0, SVB=0, SB=0;
#pragma unroll
    for (int w = 0; w < 8; w++) { SPN += red[0][w]; SPF += red[1][w]; SVB += red[2][w]; SB += red[3][w]; }
    float a1 = SVB + SPN;            // -F_normal
    float a2 = (SB - SVB) + SPF;     // -F_flipped
    float m  = fmaxf(a1, a2);
    float lse = m + logf(expf(a1 - m) + expf(a2 - m));
    atomicAdd(&g_acc, sign * (double)(-lse));
  }
}

__global__ void final_kernel(float* out) { out[0] = (float)(g_acc / (double)BATCH); }

// ---- host ----
struct K2 { uint32_t a, b; };
static inline K2 tf_child(K2 k, uint32_t i) { K2 r; tf2x32(k.a, k.b, 0u, i, r.a, r.b); return r; }

extern "C" void kernel_launch(void* const* d_in, const int* in_sizes, int n_in,
                              void* d_out, int out_size) {
  (void)in_sizes; (void)n_in; (void)out_size;
  const float* v_data = (const float*)d_in[0];
  const float* cond   = (const float*)d_in[1];
  const float* W      = (const float*)d_in[2];
  const float* b      = (const float*)d_in[3];
  const float* c      = (const float*)d_in[4];
  const float* fc1w   = (const float*)d_in[5];
  const float* fc1b   = (const float*)d_in[6];
  const float* fc2w   = (const float*)d_in[7];
  const float* fc2b   = (const float*)d_in[8];

  K2 root = {0u, 42u};
  K2 k_u = tf_child(root, 0u), k_chain = tf_child(root, 1u);
  K2 kh[KSTEPS], ku[KSTEPS], kv[KSTEPS];
  for (int s = 0; s < KSTEPS; s++) {
    K2 sk = tf_child(k_chain, (uint32_t)s);
    kh[s] = tf_child(sk, 0u); ku[s] = tf_child(sk, 1u); kv[s] = tf_child(sk, 2u);
  }

  cudaFuncSetAttribute(gemm_mma<1, true >, cudaFuncAttributeMaxDynamicSharedMemorySize, SM_TOTAL);
  cudaFuncSetAttribute(gemm_mma<1, false>, cudaFuncAttributeMaxDynamicSharedMemorySize, SM_TOTAL);
  cudaFuncSetAttribute(gemm_mma<2, false>, cudaFuncAttributeMaxDynamicSharedMemorySize, SM_TOTAL);
  cudaFuncSetAttribute(gemm_mma<4, false>, cudaFuncAttributeMaxDynamicSharedMemorySize, SM_TOTAL);

  dim3 gg(NH / 128, BATCH / 64);   // (8, 256) = 2048 CTAs

  biases_kernel<<<BATCH / BT_ROWS, 256>>>(cond, b, c, fc1w, fc1b, fc2w, fc2b);
  splitT_kernel<<<dim3(32, 32), dim3(32, 8)>>>(W);
  colsum_kernel<<<NH / 256, 256>>>(W);
  copyv_kernel<<<(BATCH * NV / 4) / 256, 256>>>(v_data);
  u0_kernel<<<BATCH / 256, 256>>>(k_u.a, k_u.b);

  for (int s = 0; s < KSTEPS; s++) {
    if (s == 0) gemm_mma<1, true ><<<gg, 256, SM_TOTAL>>>(kh[s].a, kh[s].b);
    else        gemm_mma<1, false><<<gg, 256, SM_TOTAL>>>(kh[s].a, kh[s].b);
    gemm_mma<2, false><<<gg, 256, SM_TOTAL>>>(0u, 0u);
    dEsampleV_kernel<<<BATCH, 256>>>(ku[s].a, ku[s].b, kv[s].a, kv[s].b);
  }
  fe_kernel<false, 0><<<BATCH, 256>>>(v_data, +1.0);
  gemm_mma<4, false><<<gg, 256, SM_TOTAL>>>(0u, 0u);
  fe_kernel<true, 1><<<BATCH, 256>>>(nullptr, -1.0);
  final_kernel<<<1, 1>>>((float*)d_out);
}

// round 10
// speedup vs baseline: 1.0793x; 1.0793x over previous
#include <cuda_runtime.h>
#include <cuda_bf16.h>
#include <cstdint>
#include <cmath>

#define BATCH 16384
#define NV 1024
#define NH 1024
#define HD 64
#define KSTEPS 10

__device__ float         g_bmod[(size_t)BATCH * NV];
__device__ float         g_cmod[(size_t)BATCH * NH];
__device__ float         g_a   [(size_t)BATCH * NV];
__device__ float         g_vwd [(size_t)BATCH * NV];   // recovered v_data@W for FE-data
__device__ __nv_bfloat16 g_vb  [(size_t)BATCH * NV];
__device__ __nv_bfloat16 g_hb  [(size_t)BATCH * NH];
__device__ float         g_u   [BATCH];
__device__ __nv_bfloat16 g_Whi[NV*NH], g_Wlo[NV*NH];   // [v][h] (k=h contiguous)
__device__ __nv_bfloat16 g_Thi[NV*NH], g_Tlo[NV*NH];   // [h][v] (k=v contiguous)
__device__ float         g_colsum[NH];
__device__ double        g_acc;

__host__ __device__ __forceinline__ void tf2x32(uint32_t k0, uint32_t k1,
                                                uint32_t x0, uint32_t x1,
                                                uint32_t& o0, uint32_t& o1) {
  uint32_t ks2 = k0 ^ k1 ^ 0x1BD11BDAu;
#define TF_R(r) { x0 += x1; x1 = (x1 << (r)) | (x1 >> (32 - (r))); x1 ^= x0; }
  x0 += k0; x1 += k1;
  TF_R(13) TF_R(15) TF_R(26) TF_R(6)   x0 += k1;  x1 += ks2 + 1u;
  TF_R(17) TF_R(29) TF_R(16) TF_R(24)  x0 += ks2; x1 += k0 + 2u;
  TF_R(13) TF_R(15) TF_R(26) TF_R(6)   x0 += k0;  x1 += k1 + 3u;
  TF_R(17) TF_R(29) TF_R(16) TF_R(24)  x0 += k1;  x1 += ks2 + 4u;
  TF_R(13) TF_R(15) TF_R(26) TF_R(6)   x0 += ks2; x1 += k0 + 5u;
#undef TF_R
  o0 = x0; o1 = x1;
}
__device__ __forceinline__ float jax_uniform(uint32_t ka, uint32_t kb, uint32_t idx) {
  uint32_t o0, o1; tf2x32(ka, kb, 0u, idx, o0, o1);
  return __uint_as_float(((o0 ^ o1) >> 9) | 0x3f800000u) - 1.0f;
}
__device__ __forceinline__ float sigmoidf_(float x)  { return 1.0f / (1.0f + expf(-x)); }
__device__ __forceinline__ float softplusf_(float x) { return fmaxf(x, 0.0f) + log1pf(expf(-fabsf(x))); }

__device__ __forceinline__ uint32_t smem_to_u32(const void* p) {
  uint32_t a;
  asm("{ .reg .u64 t; cvta.to.shared.u64 t, %1; cvt.u32.u64 %0, t; }" : "=r"(a) : "l"(p));
  return a;
}
__device__ __forceinline__ void sts128(uint32_t a, uint4 v) {
  asm volatile("st.shared.v4.b32 [%0], {%1,%2,%3,%4};" :: "r"(a), "r"(v.x), "r"(v.y), "r"(v.z), "r"(v.w) : "memory");
}
#define LDSM_X4(r0, r1, r2, r3, addr) \
  asm volatile("ldmatrix.sync.aligned.m8n8.x4.shared.b16 {%0,%1,%2,%3}, [%4];" \
    : "=r"(r0), "=r"(r1), "=r"(r2), "=r"(r3) : "r"(addr))

// ---------------- bf16 mma GEMM ----------------
// Tile 128x128, 16 k-blocks of 64, W = Whi + Wlo (2-way bf16 split), 2 CTAs/SM
// MODE 1: A=v_branch(g_vb,u), B=T* -> sample h into g_hb (S0: also recover vdata@W -> g_vwd)
// MODE 2: A=g_hb, B=W* -> g_a ;  MODE 4: A=g_vb, B=T* -> g_a
#define NKB 16
#define ASTR 144                       // bytes per 64-elem row (72 bf16, padded)
#define TILE_B (128 * ASTR)            // 18432
#define SM_TOTAL (6 * TILE_B)          // 110592: A0,A1,Bhi0,Bhi1,Blo0,Blo1

template<int MODE, bool S0>
__global__ void __launch_bounds__(256, 2) gemm_mma(uint32_t ka, uint32_t kb) {
  extern __shared__ char smem[];
  uint32_t sbase = smem_to_u32(smem);
  int tid = threadIdx.x, lane = tid & 31, wid = tid >> 5;
  int wm = wid & 1, wn = wid >> 1;             // warp grid 2(M) x 4(N)
  int gq = lane >> 2, tg = lane & 3;
  int bm = blockIdx.y * 128, bn = blockIdx.x * 128;

  const __nv_bfloat16* A  = (MODE == 2) ? g_hb : g_vb;
  const __nv_bfloat16* Bh = (MODE == 2) ? g_Whi : g_Thi;
  const __nv_bfloat16* Bl = (MODE == 2) ? g_Wlo : g_Tlo;

  int lrow[4]; uint32_t uxr[4];
#pragma unroll
  for (int q = 0; q < 4; q++) {
    lrow[q] = (tid >> 3) + 32 * q;
    uxr[q] = 0u;
    if (MODE == 1) uxr[q] = (g_u[bm + lrow[q]] == 0.0f) ? 0x3F803F80u : 0u;
  }
  int seg = tid & 7;

  uint4 aregs[4];
  auto ldgA = [&](int kbk) {
    int kin = kbk * 64;
#pragma unroll
    for (int q = 0; q < 4; q++) {
      uint4 v = *(const uint4*)(A + (((size_t)(bm + lrow[q])) << 10) + kin + seg * 8);
      if (MODE == 1) { v.x ^= uxr[q]; v.y ^= uxr[q]; v.z ^= uxr[q]; v.w ^= uxr[q]; }
      aregs[q] = v;
    }
  };
  auto stsA = [&](int buf) {
    uint32_t base = sbase + buf * TILE_B;
#pragma unroll
    for (int q = 0; q < 4; q++)
      sts128(base + lrow[q] * ASTR + seg * 16, aregs[q]);
  };
  auto issueB = [&](int kbk) {
    int kin = kbk * 64, buf = kbk & 1;
    uint32_t bh = sbase + (2 + buf) * TILE_B;
    uint32_t bl = sbase + (4 + buf) * TILE_B;
#pragma unroll
    for (int q = 0; q < 4; q++) {
      uint32_t soff = lrow[q] * ASTR + seg * 16;
      size_t goff = (((size_t)(bn + lrow[q])) << 10) + kin + seg * 8;
      asm volatile("cp.async.cg.shared.global [%0], [%1], 16;" :: "r"(bh + soff), "l"((const void*)(Bh + goff)) : "memory");
      asm volatile("cp.async.cg.shared.global [%0], [%1], 16;" :: "r"(bl + soff), "l"((const void*)(Bl + goff)) : "memory");
    }
    asm volatile("cp.async.commit_group;" ::: "memory");
  };

  float acc[4][4][4];
#pragma unroll
  for (int i = 0; i < 4; i++)
#pragma unroll
    for (int j = 0; j < 4; j++)
#pragma unroll
      for (int q = 0; q < 4; q++) acc[i][j][q] = 0.f;

  // prologue
  ldgA(0); stsA(0);
  issueB(0);
  ldgA(1);

  uint32_t a_l15 = (uint32_t)(lane & 15), a_hi16 = (uint32_t)((lane >> 4) << 4);
  uint32_t b_row = (uint32_t)((lane & 7) + ((lane >> 4) << 3));
  uint32_t b_k16 = (uint32_t)(((lane >> 3) & 1) << 4);

  for (int kbk = 0; kbk < NKB; kbk++) {
    if (kbk + 1 < NKB) { issueB(kbk + 1); asm volatile("cp.async.wait_group 1;" ::: "memory"); }
    else               { asm volatile("cp.async.wait_group 0;" ::: "memory"); }
    __syncthreads();
    if (kbk + 1 < NKB) stsA((kbk + 1) & 1);
    if (kbk + 2 < NKB) ldgA(kbk + 2);

    uint32_t Ab  = sbase + (kbk & 1) * TILE_B;
    uint32_t Bhb = sbase + (2 + (kbk & 1)) * TILE_B;
    uint32_t Blb = sbase + (4 + (kbk & 1)) * TILE_B;
#pragma unroll
    for (int ks = 0; ks < 4; ks++) {
      uint32_t afr[4][4];
#pragma unroll
      for (int i = 0; i < 4; i++) {
        uint32_t addr = Ab + (uint32_t)(wm * 64 + i * 16) * ASTR + a_l15 * ASTR + (uint32_t)(ks * 32) + a_hi16;
        LDSM_X4(afr[i][0], afr[i][1], afr[i][2], afr[i][3], addr);
      }
      uint32_t bhf[4][2], blf[4][2];
#pragma unroll
      for (int jp = 0; jp < 2; jp++) {
        uint32_t rowoff = ((uint32_t)(wn * 32 + jp * 16) + b_row) * ASTR + (uint32_t)(ks * 32) + b_k16;
        LDSM_X4(bhf[2*jp][0], bhf[2*jp][1], bhf[2*jp+1][0], bhf[2*jp+1][1], Bhb + rowoff);
        LDSM_X4(blf[2*jp][0], blf[2*jp][1], blf[2*jp+1][0], blf[2*jp+1][1], Blb + rowoff);
      }
#pragma unroll
      for (int i = 0; i < 4; i++)
#pragma unroll
        for (int j = 0; j < 4; j++)
          asm volatile("mma.sync.aligned.m16n8k16.row.col.f32.bf16.bf16.f32 "
            "{%0,%1,%2,%3}, {%4,%5,%6,%7}, {%8,%9}, {%0,%1,%2,%3};"
            : "+f"(acc[i][j][0]), "+f"(acc[i][j][1]), "+f"(acc[i][j][2]), "+f"(acc[i][j][3])
            : "r"(afr[i][0]), "r"(afr[i][1]), "r"(afr[i][2]), "r"(afr[i][3]),
              "r"(bhf[j][0]), "r"(bhf[j][1]));
#pragma unroll
      for (int i = 0; i < 4; i++)
#pragma unroll
        for (int j = 0; j < 4; j++)
          asm volatile("mma.sync.aligned.m16n8k16.row.col.f32.bf16.bf16.f32 "
            "{%0,%1,%2,%3}, {%4,%5,%6,%7}, {%8,%9}, {%0,%1,%2,%3};"
            : "+f"(acc[i][j][0]), "+f"(acc[i][j][1]), "+f"(acc[i][j][2]), "+f"(acc[i][j][3])
            : "r"(afr[i][0]), "r"(afr[i][1]), "r"(afr[i][2]), "r"(afr[i][3]),
              "r"(blf[j][0]), "r"(blf[j][1]));
    }
    __syncthreads();
  }

  // epilogue
#pragma unroll
  for (int i = 0; i < 4; i++) {
    int row0 = bm + wm * 64 + i * 16 + gq;
#pragma unroll
    for (int j = 0; j < 4; j++) {
      int col = bn + wn * 32 + j * 8 + tg * 2;
#pragma unroll
      for (int half = 0; half < 2; half++) {
        int r = row0 + half * 8;
        uint32_t idx = ((uint32_t)r << 10) | (uint32_t)col;
        float v0 = acc[i][j][half * 2], v1 = acc[i][j][half * 2 + 1];
        if (MODE == 1) {
          if (S0) {   // recover vdata@W: u=1 -> D ; u=0 -> colsum - D
            float uu = g_u[r];
            float w0 = (uu != 0.0f) ? v0 : g_colsum[col]     - v0;
            float w1 = (uu != 0.0f) ? v1 : g_colsum[col + 1] - v1;
            *(float2*)(g_vwd + idx) = make_float2(w0, w1);
          }
          float2 cm = *(const float2*)(g_cmod + idx);
          float p0 = sigmoidf_(v0 + cm.x), p1 = sigmoidf_(v1 + cm.y);
          float u0 = jax_uniform(ka, kb, idx), u1 = jax_uniform(ka, kb, idx + 1);
          __nv_bfloat162 hv;
          hv.x = __float2bfloat16((u0 < p0) ? 1.0f : 0.0f);
          hv.y = __float2bfloat16((u1 < p1) ? 1.0f : 0.0f);
          *(__nv_bfloat162*)(g_hb + idx) = hv;
        } else {
          *(float2*)(g_a + idx) = make_float2(v0, v1);
        }
      }
    }
  }
}

// ---- hypernetwork biases ----
#define BT_ROWS 16
__global__ void biases_kernel(const float* __restrict__ cond, const float* __restrict__ b,
                              const float* __restrict__ c, const float* __restrict__ fc1w,
                              const float* __restrict__ fc1b, const float* __restrict__ fc2w,
                              const float* __restrict__ fc2b) {
  __shared__ float xs[BT_ROWS][HD];
  int r0 = blockIdx.x * BT_ROWS, tid = threadIdx.x;
  for (int t = tid; t < BT_ROWS * HD; t += blockDim.x) {
    int r = t / HD, d = t % HD;
    xs[r][d] = tanhf(cond[r0 + r] * fc1w[d] + fc1b[d]);
  }
  __syncthreads();
  for (int j = tid; j < NV + NH; j += blockDim.x) {
    int gw, bw;
    if (j < NV) { gw = j; bw = NV + j; } else { gw = 2*NV + (j-NV); bw = 2*NV + NH + (j-NV); }
    const float* wg = fc2w + (size_t)gw * HD;
    const float* wb = fc2w + (size_t)bw * HD;
    float accG[BT_ROWS], accB[BT_ROWS];
#pragma unroll
    for (int r = 0; r < BT_ROWS; r++) { accG[r] = 0.f; accB[r] = 0.f; }
    for (int d = 0; d < HD; d++) {
      float g = wg[d], bb = wb[d];
#pragma unroll
      for (int r = 0; r < BT_ROWS; r++) { float x = xs[r][d]; accG[r] += g*x; accB[r] += bb*x; }
    }
    float gb = fc2b[gw], bbia = fc2b[bw];
    if (j < NV) {
      float bj = b[j];
      for (int r = 0; r < BT_ROWS; r++)
        g_bmod[(size_t)(r0 + r)*NV + j] = (1.0f + accG[r] + gb)*bj + (accB[r] + bbia);
    } else {
      int hh = j - NV; float ch = c[hh];
      for (int r = 0; r < BT_ROWS; r++)
        g_cmod[(size_t)(r0 + r)*NH + hh] = (1.0f + accG[r] + gb)*ch + (accB[r] + bbia);
    }
  }
}

// ---- W 2-way split, both layouts ----
__device__ __forceinline__ void split2(float w, __nv_bfloat16& hi, __nv_bfloat16& lo) {
  hi = __float2bfloat16(w);
  lo = __float2bfloat16(w - __bfloat162float(hi));
}
__global__ void splitT_kernel(const float* __restrict__ W) {
  __shared__ float t[32][33];
  int bx = blockIdx.x*32, by = blockIdx.y*32;
  int tx = threadIdx.x, ty = threadIdx.y;
  for (int i = 0; i < 32; i += 8) {
    int r = by + ty + i, cc = bx + tx;
    float w = W[(size_t)r*NH + cc];
    t[ty + i][tx] = w;
    __nv_bfloat16 hi, lo; split2(w, hi, lo);
    size_t ix = (size_t)r*NH + cc;
    g_Whi[ix] = hi; g_Wlo[ix] = lo;
  }
  __syncthreads();
  for (int i = 0; i < 32; i += 8) {
    float w = t[tx][ty + i];
    __nv_bfloat16 hi, lo; split2(w, hi, lo);
    size_t ix = (size_t)(bx + ty + i)*NV + by + tx;
    g_Thi[ix] = hi; g_Tlo[ix] = lo;
  }
}

__global__ void colsum_kernel(const float* __restrict__ W) {
  int h = blockIdx.x * blockDim.x + threadIdx.x;
  float s = 0.f;
  for (int v2 = 0; v2 < NV; v2++) s += W[(size_t)v2*NH + h];
  g_colsum[h] = s;
}
__global__ void copyv_kernel(const float* __restrict__ v_data) {
  int i = blockIdx.x * blockDim.x + threadIdx.x;
  float4 v = ((const float4*)v_data)[i];
  ushort4 o;
  o.x = __bfloat16_as_ushort(__float2bfloat16(v.x));
  o.y = __bfloat16_as_ushort(__float2bfloat16(v.y));
  o.z = __bfloat16_as_ushort(__float2bfloat16(v.z));
  o.w = __bfloat16_as_ushort(__float2bfloat16(v.w));
  ((ushort4*)g_vb)[i] = o;
}
__global__ void u0_kernel(uint32_t ka, uint32_t kb) {
  int i = blockIdx.x * blockDim.x + threadIdx.x;
  if (i == 0) g_acc = 0.0;
  if (i < BATCH) g_u[i] = (jax_uniform(ka, kb, (uint32_t)i) < 0.5f) ? 1.0f : 0.0f;
}

// ---- fused dE + sample u + sample v ----
__global__ void dEsampleV_kernel(uint32_t kua, uint32_t kub, uint32_t kva, uint32_t kvb) {
  int row = blockIdx.x, tid = threadIdx.x, wrp = tid >> 5, lane = tid & 31;
  const float4 a4 = ((const float4*)(g_a    + (size_t)row*NV))[tid];
  const float4 b4 = ((const float4*)(g_bmod + (size_t)row*NV))[tid];
  ushort4 vu = ((const ushort4*)(g_vb + (size_t)row*NV))[tid];
  float v0 = __bfloat162float(__ushort_as_bfloat16(vu.x));
  float v1 = __bfloat162float(__ushort_as_bfloat16(vu.y));
  float v2 = __bfloat162float(__ushort_as_bfloat16(vu.z));
  float v3 = __bfloat162float(__ushort_as_bfloat16(vu.w));
  float sa = a4.x+a4.y+a4.z+a4.w, sb = b4.x+b4.y+b4.z+b4.w;
  float sva = v0*a4.x+v1*a4.y+v2*a4.z+v3*a4.w, svb = v0*b4.x+v1*b4.y+v2*b4.z+v3*b4.w;
#pragma unroll
  for (int o = 16; o > 0; o >>= 1) {
    sa  += __shfl_down_sync(0xffffffffu, sa,  o);
    sb  += __shfl_down_sync(0xffffffffu, sb,  o);
    sva += __shfl_down_sync(0xffffffffu, sva, o);
    svb += __shfl_down_sync(0xffffffffu, svb, o);
  }
  __shared__ float red[4][8];
  __shared__ float uval;
  if (lane == 0) { red[0][wrp] = sa; red[1][wrp] = sb; red[2][wrp] = sva; red[3][wrp] = svb; }
  __syncthreads();
  if (tid == 0) {
    float SA=0, SB=0, SVA=0, SVB=0;
#pragma unroll
    for (int w = 0; w < 8; w++) { SA += red[0][w]; SB += red[1][w]; SVA += red[2][w]; SVB += red[3][w]; }
    float dE = -SB - SA + 2.0f*SVB + 2.0f*SVA;
    float un = jax_uniform(kua, kub, (uint32_t)row);
    float u  = (un < sigmoidf_(dE)) ? 1.0f : 0.0f;
    g_u[row] = u; uval = u;
  }
  __syncthreads();
  float u = uval;
  float aa[4] = {a4.x, a4.y, a4.z, a4.w}, bb[4] = {b4.x, b4.y, b4.z, b4.w};
  ushort4 outv; unsigned short* op = (unsigned short*)&outv;
#pragma unroll
  for (int q = 0; q < 4; q++) {
    uint32_t idx = (uint32_t)row*1024u + (uint32_t)(tid*4 + q);
    float p  = sigmoidf_(aa[q] + bb[q]);
    float un = jax_uniform(kva, kvb, idx);
    float vb = (un < p) ? 1.0f : 0.0f;
    op[q] = __bfloat16_as_ushort(__float2bfloat16((u != 0.0f) ? vb : 1.0f - vb));
  }
  ((ushort4*)(g_vb + (size_t)row*NV))[tid] = outv;
}

// ---- free energy ----
// USE_GV: v from g_vb (model) else vparam (data). WSRC 0: vW from g_vwd ; 1: from g_a
template<bool USE_GV, int WSRC>
__global__ void fe_kernel(const float* __restrict__ vparam, double sign) {
  int row = blockIdx.x, tid = threadIdx.x, wrp = tid >> 5, lane = tid & 31;
  const float* br = g_bmod + (size_t)row*NV;
  const float* wr = (WSRC == 0 ? g_vwd : g_a) + (size_t)row*NH;
  const float* cr = g_cmod + (size_t)row*NH;
  float spn = 0, spf = 0, svb = 0, sb = 0;
  for (int j = tid; j < NV; j += 256) {
    float vv = USE_GV ? __bfloat162float(g_vb[(size_t)row*NV + j]) : vparam[(size_t)row*NV + j];
    float bbv = br[j];
    svb += vv*bbv; sb += bbv;
    float w = wr[j], cm = cr[j];
    spn += softplusf_(w + cm);
    spf += softplusf_(g_colsum[j] - w + cm);
  }
#pragma unroll
  for (int o = 16; o > 0; o >>= 1) {
    spn += __shfl_down_sync(0xffffffffu, spn, o);
    spf += __shfl_down_sync(0xffffffffu, spf, o);
    svb += __shfl_down_sync(0xffffffffu, svb, o);
    sb  += __shfl_down_sync(0xffffffffu, sb,  o);
  }
  __shared__ float red[4][8];
  if (lane == 0) { red[0][wrp] = spn; red[1][wrp] = spf; red[2][wrp] = svb; red[3][wrp] = sb; }
  __syncthreads();
  if (tid == 0) {
    float SPN=0, SPF=0, SVB=0, SB=0;
#pragma unroll
    for (int w = 0; w < 8; w++) { SPN += red[0][w]; SPF += red[1][w]; SVB += red[2][w]; SB += red[3][w]; }
    float a1 = SVB + SPN;            // -F_normal
    float a2 = (SB - SVB) + SPF;     // -F_flipped
    float m  = fmaxf(a1, a2);
    float lse = m + logf(expf(a1 - m) + expf(a2 - m));
    atomicAdd(&g_acc, sign * (double)(-lse));
  }
}

__global__ void final_kernel(float* out) { out[0] = (float)(g_acc / (double)BATCH); }

// ---- host ----
struct K2 { uint32_t a, b; };
static inline K2 tf_child(K2 k, uint32_t i) { K2 r; tf2x32(k.a, k.b, 0u, i, r.a, r.b); return r; }

extern "C" void kernel_launch(void* const* d_in, const int* in_sizes, int n_in,
                              void* d_out, int out_size) {
  (void)in_sizes; (void)n_in; (void)out_size;
  const float* v_data = (const float*)d_in[0];
  const float* cond   = (const float*)d_in[1];
  const float* W      = (const float*)d_in[2];
  const float* b      = (const float*)d_in[3];
  const float* c      = (const float*)d_in[4];
  const float* fc1w   = (const float*)d_in[5];
  const float* fc1b   = (const float*)d_in[6];
  const float* fc2w   = (const float*)d_in[7];
  const float* fc2b   = (const float*)d_in[8];

  K2 root = {0u, 42u};
  K2 k_u = tf_child(root, 0u), k_chain = tf_child(root, 1u);
  K2 kh[KSTEPS], ku[KSTEPS], kv[KSTEPS];
  for (int s = 0; s < KSTEPS; s++) {
    K2 sk = tf_child(k_chain, (uint32_t)s);
    kh[s] = tf_child(sk, 0u); ku[s] = tf_child(sk, 1u); kv[s] = tf_child(sk, 2u);
  }

  cudaFuncSetAttribute(gemm_mma<1, true >, cudaFuncAttributeMaxDynamicSharedMemorySize, SM_TOTAL);
  cudaFuncSetAttribute(gemm_mma<1, false>, cudaFuncAttributeMaxDynamicSharedMemorySize, SM_TOTAL);
  cudaFuncSetAttribute(gemm_mma<2, false>, cudaFuncAttributeMaxDynamicSharedMemorySize, SM_TOTAL);
  cudaFuncSetAttribute(gemm_mma<4, false>, cudaFuncAttributeMaxDynamicSharedMemorySize, SM_TOTAL);

  dim3 gg(NH / 128, BATCH / 128);   // (8, 128) = 1024 CTAs

  biases_kernel<<<BATCH / BT_ROWS, 256>>>(cond, b, c, fc1w, fc1b, fc2w, fc2b);
  splitT_kernel<<<dim3(32, 32), dim3(32, 8)>>>(W);
  colsum_kernel<<<NH / 256, 256>>>(W);
  copyv_kernel<<<(BATCH * NV / 4) / 256, 256>>>(v_data);
  u0_kernel<<<BATCH / 256, 256>>>(k_u.a, k_u.b);

  for (int s = 0; s < KSTEPS; s++) {
    if (s == 0) gemm_mma<1, true ><<<gg, 256, SM_TOTAL>>>(kh[s].a, kh[s].b);
    else        gemm_mma<1, false><<<gg, 256, SM_TOTAL>>>(kh[s].a, kh[s].b);
    gemm_mma<2, false><<<gg, 256, SM_TOTAL>>>(0u, 0u);
    dEsampleV_kernel<<<BATCH, 256>>>(ku[s].a, ku[s].b, kv[s].a, kv[s].b);
  }
  fe_kernel<false, 0><<<BATCH, 256>>>(v_data, +1.0);
  gemm_mma<4, false><<<gg, 256, SM_TOTAL>>>(0u, 0u);
  fe_kernel<true, 1><<<BATCH, 256>>>(nullptr, -1.0);
  final_kernel<<<1, 1>>>((float*)d_out);
}

// round 11
// speedup vs baseline: 1.1123x; 1.0306x over previous
#include <cuda_runtime.h>
#include <cuda_bf16.h>
#include <cstdint>
#include <cmath>

#define BATCH 16384
#define NV 1024
#define NH 1024
#define HD 64
#define KSTEPS 10

__device__ float         g_bmod[(size_t)BATCH * NV];
__device__ float         g_cmod[(size_t)BATCH * NH];
__device__ float         g_a   [(size_t)BATCH * NV];   // vW of v_model (MODE 4 only)
__device__ float         g_vwd [(size_t)BATCH * NV];   // recovered v_data@W for FE-data
__device__ __nv_bfloat16 g_vb  [(size_t)BATCH * NV];   // v_data, then vbn chain state
__device__ __nv_bfloat16 g_hb  [(size_t)BATCH * NH];
__device__ float         g_u   [BATCH];                // u0 only (loss is u-invariant)
__device__ __nv_bfloat16 g_Whi[NV*NH], g_Wlo[NV*NH];   // [v][h] (k=h contiguous)
__device__ __nv_bfloat16 g_Thi[NV*NH], g_Tlo[NV*NH];   // [h][v] (k=v contiguous)
__device__ float         g_colsum[NH];
__device__ double        g_acc;

__host__ __device__ __forceinline__ void tf2x32(uint32_t k0, uint32_t k1,
                                                uint32_t x0, uint32_t x1,
                                                uint32_t& o0, uint32_t& o1) {
  uint32_t ks2 = k0 ^ k1 ^ 0x1BD11BDAu;
#define TF_R(r) { x0 += x1; x1 = (x1 << (r)) | (x1 >> (32 - (r))); x1 ^= x0; }
  x0 += k0; x1 += k1;
  TF_R(13) TF_R(15) TF_R(26) TF_R(6)   x0 += k1;  x1 += ks2 + 1u;
  TF_R(17) TF_R(29) TF_R(16) TF_R(24)  x0 += ks2; x1 += k0 + 2u;
  TF_R(13) TF_R(15) TF_R(26) TF_R(6)   x0 += k0;  x1 += k1 + 3u;
  TF_R(17) TF_R(29) TF_R(16) TF_R(24)  x0 += k1;  x1 += ks2 + 4u;
  TF_R(13) TF_R(15) TF_R(26) TF_R(6)   x0 += ks2; x1 += k0 + 5u;
#undef TF_R
  o0 = x0; o1 = x1;
}
__device__ __forceinline__ float jax_uniform(uint32_t ka, uint32_t kb, uint32_t idx) {
  uint32_t o0, o1; tf2x32(ka, kb, 0u, idx, o0, o1);
  return __uint_as_float(((o0 ^ o1) >> 9) | 0x3f800000u) - 1.0f;
}
__device__ __forceinline__ float sigmoidf_(float x)  { return 1.0f / (1.0f + expf(-x)); }
__device__ __forceinline__ float softplusf_(float x) { return fmaxf(x, 0.0f) + log1pf(expf(-fabsf(x))); }

__device__ __forceinline__ uint32_t smem_to_u32(const void* p) {
  uint32_t a;
  asm("{ .reg .u64 t; cvta.to.shared.u64 t, %1; cvt.u32.u64 %0, t; }" : "=r"(a) : "l"(p));
  return a;
}
__device__ __forceinline__ void sts128(uint32_t a, uint4 v) {
  asm volatile("st.shared.v4.b32 [%0], {%1,%2,%3,%4};" :: "r"(a), "r"(v.x), "r"(v.y), "r"(v.z), "r"(v.w) : "memory");
}
#define LDSM_X4(r0, r1, r2, r3, addr) \
  asm volatile("ldmatrix.sync.aligned.m8n8.x4.shared.b16 {%0,%1,%2,%3}, [%4];" \
    : "=r"(r0), "=r"(r1), "=r"(r2), "=r"(r3) : "r"(addr))

// ---------------- bf16 mma GEMM ----------------
// Tile 128x128, 16 k-blocks of 64, W = Whi + Wlo (2-way bf16 split), 2 CTAs/SM
// MODE 1: A=g_vb (FLIP: xor by u), B=T* -> sample h into g_hb (S0: recover vdata@W -> g_vwd)
// MODE 2: A=g_hb, B=W* -> sample vbn into g_vb (reads g_bmod; writes NO g_a)
// MODE 4: A=g_vb, B=T* -> write g_a (for FE-model)
#define NKB 16
#define ASTR 144                       // bytes per 64-elem row (72 bf16, padded)
#define TILE_B (128 * ASTR)            // 18432
#define SM_TOTAL (6 * TILE_B)          // 110592: A0,A1,Bhi0,Bhi1,Blo0,Blo1

template<int MODE, bool S0, bool FLIP>
__global__ void __launch_bounds__(256, 2) gemm_mma(uint32_t ka, uint32_t kb) {
  extern __shared__ char smem[];
  uint32_t sbase = smem_to_u32(smem);
  int tid = threadIdx.x, lane = tid & 31, wid = tid >> 5;
  int wm = wid & 1, wn = wid >> 1;             // warp grid 2(M) x 4(N)
  int gq = lane >> 2, tg = lane & 3;
  int bm = blockIdx.y * 128, bn = blockIdx.x * 128;

  const __nv_bfloat16* A  = (MODE == 2) ? g_hb : g_vb;
  const __nv_bfloat16* Bh = (MODE == 2) ? g_Whi : g_Thi;
  const __nv_bfloat16* Bl = (MODE == 2) ? g_Wlo : g_Tlo;

  int lrow[4]; uint32_t uxr[4];
#pragma unroll
  for (int q = 0; q < 4; q++) {
    lrow[q] = (tid >> 3) + 32 * q;
    uxr[q] = 0u;
    if (FLIP) uxr[q] = (g_u[bm + lrow[q]] == 0.0f) ? 0x3F803F80u : 0u;
  }
  int seg = tid & 7;

  uint4 aregs[4];
  auto ldgA = [&](int kbk) {
    int kin = kbk * 64;
#pragma unroll
    for (int q = 0; q < 4; q++) {
      uint4 v = *(const uint4*)(A + (((size_t)(bm + lrow[q])) << 10) + kin + seg * 8);
      if (FLIP) { v.x ^= uxr[q]; v.y ^= uxr[q]; v.z ^= uxr[q]; v.w ^= uxr[q]; }
      aregs[q] = v;
    }
  };
  auto stsA = [&](int buf) {
    uint32_t base = sbase + buf * TILE_B;
#pragma unroll
    for (int q = 0; q < 4; q++)
      sts128(base + lrow[q] * ASTR + seg * 16, aregs[q]);
  };
  auto issueB = [&](int kbk) {
    int kin = kbk * 64, buf = kbk & 1;
    uint32_t bh = sbase + (2 + buf) * TILE_B;
    uint32_t bl = sbase + (4 + buf) * TILE_B;
#pragma unroll
    for (int q = 0; q < 4; q++) {
      uint32_t soff = lrow[q] * ASTR + seg * 16;
      size_t goff = (((size_t)(bn + lrow[q])) << 10) + kin + seg * 8;
      asm volatile("cp.async.cg.shared.global [%0], [%1], 16;" :: "r"(bh + soff), "l"((const void*)(Bh + goff)) : "memory");
      asm volatile("cp.async.cg.shared.global [%0], [%1], 16;" :: "r"(bl + soff), "l"((const void*)(Bl + goff)) : "memory");
    }
    asm volatile("cp.async.commit_group;" ::: "memory");
  };

  float acc[4][4][4];
#pragma unroll
  for (int i = 0; i < 4; i++)
#pragma unroll
    for (int j = 0; j < 4; j++)
#pragma unroll
      for (int q = 0; q < 4; q++) acc[i][j][q] = 0.f;

  // prologue
  ldgA(0); stsA(0);
  issueB(0);
  ldgA(1);

  uint32_t a_l15 = (uint32_t)(lane & 15), a_hi16 = (uint32_t)((lane >> 4) << 4);
  uint32_t b_row = (uint32_t)((lane & 7) + ((lane >> 4) << 3));
  uint32_t b_k16 = (uint32_t)(((lane >> 3) & 1) << 4);

  for (int kbk = 0; kbk < NKB; kbk++) {
    if (kbk + 1 < NKB) { issueB(kbk + 1); asm volatile("cp.async.wait_group 1;" ::: "memory"); }
    else               { asm volatile("cp.async.wait_group 0;" ::: "memory"); }
    __syncthreads();
    if (kbk + 1 < NKB) stsA((kbk + 1) & 1);
    if (kbk + 2 < NKB) ldgA(kbk + 2);

    uint32_t Ab  = sbase + (kbk & 1) * TILE_B;
    uint32_t Bhb = sbase + (2 + (kbk & 1)) * TILE_B;
    uint32_t Blb = sbase + (4 + (kbk & 1)) * TILE_B;
#pragma unroll
    for (int ks = 0; ks < 4; ks++) {
      uint32_t afr[4][4];
#pragma unroll
      for (int i = 0; i < 4; i++) {
        uint32_t addr = Ab + (uint32_t)(wm * 64 + i * 16) * ASTR + a_l15 * ASTR + (uint32_t)(ks * 32) + a_hi16;
        LDSM_X4(afr[i][0], afr[i][1], afr[i][2], afr[i][3], addr);
      }
      uint32_t bhf[4][2], blf[4][2];
#pragma unroll
      for (int jp = 0; jp < 2; jp++) {
        uint32_t rowoff = ((uint32_t)(wn * 32 + jp * 16) + b_row) * ASTR + (uint32_t)(ks * 32) + b_k16;
        LDSM_X4(bhf[2*jp][0], bhf[2*jp][1], bhf[2*jp+1][0], bhf[2*jp+1][1], Bhb + rowoff);
        LDSM_X4(blf[2*jp][0], blf[2*jp][1], blf[2*jp+1][0], blf[2*jp+1][1], Blb + rowoff);
      }
#pragma unroll
      for (int i = 0; i < 4; i++)
#pragma unroll
        for (int j = 0; j < 4; j++)
          asm volatile("mma.sync.aligned.m16n8k16.row.col.f32.bf16.bf16.f32 "
            "{%0,%1,%2,%3}, {%4,%5,%6,%7}, {%8,%9}, {%0,%1,%2,%3};"
            : "+f"(acc[i][j][0]), "+f"(acc[i][j][1]), "+f"(acc[i][j][2]), "+f"(acc[i][j][3])
            : "r"(afr[i][0]), "r"(afr[i][1]), "r"(afr[i][2]), "r"(afr[i][3]),
              "r"(bhf[j][0]), "r"(bhf[j][1]));
#pragma unroll
      for (int i = 0; i < 4; i++)
#pragma unroll
        for (int j = 0; j < 4; j++)
          asm volatile("mma.sync.aligned.m16n8k16.row.col.f32.bf16.bf16.f32 "
            "{%0,%1,%2,%3}, {%4,%5,%6,%7}, {%8,%9}, {%0,%1,%2,%3};"
            : "+f"(acc[i][j][0]), "+f"(acc[i][j][1]), "+f"(acc[i][j][2]), "+f"(acc[i][j][3])
            : "r"(afr[i][0]), "r"(afr[i][1]), "r"(afr[i][2]), "r"(afr[i][3]),
              "r"(blf[j][0]), "r"(blf[j][1]));
    }
    __syncthreads();
  }

  // epilogue
#pragma unroll
  for (int i = 0; i < 4; i++) {
    int row0 = bm + wm * 64 + i * 16 + gq;
#pragma unroll
    for (int j = 0; j < 4; j++) {
      int col = bn + wn * 32 + j * 8 + tg * 2;
#pragma unroll
      for (int half = 0; half < 2; half++) {
        int r = row0 + half * 8;
        uint32_t idx = ((uint32_t)r << 10) | (uint32_t)col;
        float v0 = acc[i][j][half * 2], v1 = acc[i][j][half * 2 + 1];
        if (MODE == 1) {
          if (S0) {   // recover vdata@W: u=1 -> D ; u=0 -> colsum - D
            float uu = g_u[r];
            float w0 = (uu != 0.0f) ? v0 : g_colsum[col]     - v0;
            float w1 = (uu != 0.0f) ? v1 : g_colsum[col + 1] - v1;
            *(float2*)(g_vwd + idx) = make_float2(w0, w1);
          }
          float2 cm = *(const float2*)(g_cmod + idx);
          float p0 = sigmoidf_(v0 + cm.x), p1 = sigmoidf_(v1 + cm.y);
          float u0 = jax_uniform(ka, kb, idx), u1 = jax_uniform(ka, kb, idx + 1);
          __nv_bfloat162 hv;
          hv.x = __float2bfloat16((u0 < p0) ? 1.0f : 0.0f);
          hv.y = __float2bfloat16((u1 < p1) ? 1.0f : 0.0f);
          *(__nv_bfloat162*)(g_hb + idx) = hv;
        } else if (MODE == 2) {
          // sample vbn = Bernoulli(sigmoid(a + b_mod)) directly; v_branch of next
          // step equals vbn identically (u-flip cancels), loss is u-invariant.
          float2 bm2 = *(const float2*)(g_bmod + idx);
          float p0 = sigmoidf_(v0 + bm2.x), p1 = sigmoidf_(v1 + bm2.y);
          float u0 = jax_uniform(ka, kb, idx), u1 = jax_uniform(ka, kb, idx + 1);
          __nv_bfloat162 vv;
          vv.x = __float2bfloat16((u0 < p0) ? 1.0f : 0.0f);
          vv.y = __float2bfloat16((u1 < p1) ? 1.0f : 0.0f);
          *(__nv_bfloat162*)(g_vb + idx) = vv;
        } else {
          *(float2*)(g_a + idx) = make_float2(v0, v1);
        }
      }
    }
  }
}

// ---- hypernetwork biases ----
#define BT_ROWS 16
__global__ void biases_kernel(const float* __restrict__ cond, const float* __restrict__ b,
                              const float* __restrict__ c, const float* __restrict__ fc1w,
                              const float* __restrict__ fc1b, const float* __restrict__ fc2w,
                              const float* __restrict__ fc2b) {
  __shared__ float xs[BT_ROWS][HD];
  int r0 = blockIdx.x * BT_ROWS, tid = threadIdx.x;
  for (int t = tid; t < BT_ROWS * HD; t += blockDim.x) {
    int r = t / HD, d = t % HD;
    xs[r][d] = tanhf(cond[r0 + r] * fc1w[d] + fc1b[d]);
  }
  __syncthreads();
  for (int j = tid; j < NV + NH; j += blockDim.x) {
    int gw, bw;
    if (j < NV) { gw = j; bw = NV + j; } else { gw = 2*NV + (j-NV); bw = 2*NV + NH + (j-NV); }
    const float* wg = fc2w + (size_t)gw * HD;
    const float* wb = fc2w + (size_t)bw * HD;
    float accG[BT_ROWS], accB[BT_ROWS];
#pragma unroll
    for (int r = 0; r < BT_ROWS; r++) { accG[r] = 0.f; accB[r] = 0.f; }
    for (int d = 0; d < HD; d++) {
      float g = wg[d], bb = wb[d];
#pragma unroll
      for (int r = 0; r < BT_ROWS; r++) { float x = xs[r][d]; accG[r] += g*x; accB[r] += bb*x; }
    }
    float gb = fc2b[gw], bbia = fc2b[bw];
    if (j < NV) {
      float bj = b[j];
      for (int r = 0; r < BT_ROWS; r++)
        g_bmod[(size_t)(r0 + r)*NV + j] = (1.0f + accG[r] + gb)*bj + (accB[r] + bbia);
    } else {
      int hh = j - NV; float ch = c[hh];
      for (int r = 0; r < BT_ROWS; r++)
        g_cmod[(size_t)(r0 + r)*NH + hh] = (1.0f + accG[r] + gb)*ch + (accB[r] + bbia);
    }
  }
}

// ---- W 2-way split, both layouts ----
__device__ __forceinline__ void split2(float w, __nv_bfloat16& hi, __nv_bfloat16& lo) {
  hi = __float2bfloat16(w);
  lo = __float2bfloat16(w - __bfloat162float(hi));
}
__global__ void splitT_kernel(const float* __restrict__ W) {
  __shared__ float t[32][33];
  int bx = blockIdx.x*32, by = blockIdx.y*32;
  int tx = threadIdx.x, ty = threadIdx.y;
  for (int i = 0; i < 32; i += 8) {
    int r = by + ty + i, cc = bx + tx;
    float w = W[(size_t)r*NH + cc];
    t[ty + i][tx] = w;
    __nv_bfloat16 hi, lo; split2(w, hi, lo);
    size_t ix = (size_t)r*NH + cc;
    g_Whi[ix] = hi; g_Wlo[ix] = lo;
  }
  __syncthreads();
  for (int i = 0; i < 32; i += 8) {
    float w = t[tx][ty + i];
    __nv_bfloat16 hi, lo; split2(w, hi, lo);
    size_t ix = (size_t)(bx + ty + i)*NV + by + tx;
    g_Thi[ix] = hi; g_Tlo[ix] = lo;
  }
}

__global__ void colsum_kernel(const float* __restrict__ W) {
  int h = blockIdx.x * blockDim.x + threadIdx.x;
  float s = 0.f;
  for (int v2 = 0; v2 < NV; v2++) s += W[(size_t)v2*NH + h];
  g_colsum[h] = s;
}
__global__ void copyv_kernel(const float* __restrict__ v_data) {
  int i = blockIdx.x * blockDim.x + threadIdx.x;
  float4 v = ((const float4*)v_data)[i];
  ushort4 o;
  o.x = __bfloat16_as_ushort(__float2bfloat16(v.x));
  o.y = __bfloat16_as_ushort(__float2bfloat16(v.y));
  o.z = __bfloat16_as_ushort(__float2bfloat16(v.z));
  o.w = __bfloat16_as_ushort(__float2bfloat16(v.w));
  ((ushort4*)g_vb)[i] = o;
}
__global__ void u0_kernel(uint32_t ka, uint32_t kb) {
  int i = blockIdx.x * blockDim.x + threadIdx.x;
  if (i == 0) g_acc = 0.0;
  if (i < BATCH) g_u[i] = (jax_uniform(ka, kb, (uint32_t)i) < 0.5f) ? 1.0f : 0.0f;
}

// ---- free energy ----
// USE_GV: v from g_vb (model) else vparam (data). WSRC 0: vW from g_vwd ; 1: from g_a
template<bool USE_GV, int WSRC>
__global__ void fe_kernel(const float* __restrict__ vparam, double sign) {
  int row = blockIdx.x, tid = threadIdx.x, wrp = tid >> 5, lane = tid & 31;
  const float* br = g_bmod + (size_t)row*NV;
  const float* wr = (WSRC == 0 ? g_vwd : g_a) + (size_t)row*NH;
  const float* cr = g_cmod + (size_t)row*NH;
  float spn = 0, spf = 0, svb = 0, sb = 0;
  for (int j = tid; j < NV; j += 256) {
    float vv = USE_GV ? __bfloat162float(g_vb[(size_t)row*NV + j]) : vparam[(size_t)row*NV + j];
    float bbv = br[j];
    svb += vv*bbv; sb += bbv;
    float w = wr[j], cm = cr[j];
    spn += softplusf_(w + cm);
    spf += softplusf_(g_colsum[j] - w + cm);
  }
#pragma unroll
  for (int o = 16; o > 0; o >>= 1) {
    spn += __shfl_down_sync(0xffffffffu, spn, o);
    spf += __shfl_down_sync(0xffffffffu, spf, o);
    svb += __shfl_down_sync(0xffffffffu, svb, o);
    sb  += __shfl_down_sync(0xffffffffu, sb,  o);
  }
  __shared__ float red[4][8];
  if (lane == 0) { red[0][wrp] = spn; red[1][wrp] = spf; red[2][wrp] = svb; red[3][wrp] = sb; }
  __syncthreads();
  if (tid == 0) {
    float SPN=0, SPF=0, SVB=0, SB=0;
#pragma unroll
    for (int w = 0; w < 8; w++) { SPN += red[0][w]; SPF += red[1][w]; SVB += red[2][w]; SB += red[3][w]; }
    float a1 = SVB + SPN;            // -F_normal
    float a2 = (SB - SVB) + SPF;     // -F_flipped
    float m  = fmaxf(a1, a2);
    float lse = m + logf(expf(a1 - m) + expf(a2 - m));
    atomicAdd(&g_acc, sign * (double)(-lse));
  }
}

__global__ void final_kernel(float* out) { out[0] = (float)(g_acc / (double)BATCH); }

// ---- host ----
struct K2 { uint32_t a, b; };
static inline K2 tf_child(K2 k, uint32_t i) { K2 r; tf2x32(k.a, k.b, 0u, i, r.a, r.b); return r; }

extern "C" void kernel_launch(void* const* d_in, const int* in_sizes, int n_in,
                              void* d_out, int out_size) {
  (void)in_sizes; (void)n_in; (void)out_size;
  const float* v_data = (const float*)d_in[0];
  const float* cond   = (const float*)d_in[1];
  const float* W      = (const float*)d_in[2];
  const float* b      = (const float*)d_in[3];
  const float* c      = (const float*)d_in[4];
  const float* fc1w   = (const float*)d_in[5];
  const float* fc1b   = (const float*)d_in[6];
  const float* fc2w   = (const float*)d_in[7];
  const float* fc2b   = (const float*)d_in[8];

  K2 root = {0u, 42u};
  K2 k_u = tf_child(root, 0u), k_chain = tf_child(root, 1u);
  K2 kh[KSTEPS], kv[KSTEPS];
  for (int s = 0; s < KSTEPS; s++) {
    K2 sk = tf_child(k_chain, (uint32_t)s);
    kh[s] = tf_child(sk, 0u);
    kv[s] = tf_child(sk, 2u);   // ku (index 1) unused: loss is u-invariant
  }

  cudaFuncSetAttribute(gemm_mma<1, true , true >, cudaFuncAttributeMaxDynamicSharedMemorySize, SM_TOTAL);
  cudaFuncSetAttribute(gemm_mma<1, false, false>, cudaFuncAttributeMaxDynamicSharedMemorySize, SM_TOTAL);
  cudaFuncSetAttribute(gemm_mma<2, false, false>, cudaFuncAttributeMaxDynamicSharedMemorySize, SM_TOTAL);
  cudaFuncSetAttribute(gemm_mma<4, false, false>, cudaFuncAttributeMaxDynamicSharedMemorySize, SM_TOTAL);

  dim3 gg(NH / 128, BATCH / 128);   // (8, 128) = 1024 CTAs

  biases_kernel<<<BATCH / BT_ROWS, 256>>>(cond, b, c, fc1w, fc1b, fc2w, fc2b);
  splitT_kernel<<<dim3(32, 32), dim3(32, 8)>>>(W);
  colsum_kernel<<<NH / 256, 256>>>(W);
  copyv_kernel<<<(BATCH * NV / 4) / 256, 256>>>(v_data);
  u0_kernel<<<BATCH / 256, 256>>>(k_u.a, k_u.b);

  for (int s = 0; s < KSTEPS; s++) {
    if (s == 0) gemm_mma<1, true , true ><<<gg, 256, SM_TOTAL>>>(kh[s].a, kh[s].b);
    else        gemm_mma<1, false, false><<<gg, 256, SM_TOTAL>>>(kh[s].a, kh[s].b);
    gemm_mma<2, false, false><<<gg, 256, SM_TOTAL>>>(kv[s].a, kv[s].b);
  }
  fe_kernel<false, 0><<<BATCH, 256>>>(v_data, +1.0);
  gemm_mma<4, false, false><<<gg, 256, SM_TOTAL>>>(0u, 0u);   // vbn_9 @ W -> g_a
  fe_kernel<true, 1><<<BATCH, 256>>>(nullptr, -1.0);
  final_kernel<<<1, 1>>>((float*)d_out);
}